// round 14
// baseline (speedup 1.0000x reference)
#include <cuda_runtime.h>

#define NN 50000
#define MM 20

typedef unsigned long long u64;

// Per-node precompute scratch: [em1_i+b | em1_j | ogh_i+b | ogh_j | pei+b | pej+b]
// 6 x 64 floats per node.
__device__ float g_P[NN * 384];

// ---------- packed f32x2 helpers ----------
__device__ __forceinline__ u64 pack2(float lo, float hi) {
    u64 r;
    asm("mov.b64 %0, {%1,%2};" : "=l"(r) : "f"(lo), "f"(hi));
    return r;
}
__device__ __forceinline__ float2 unpack2(u64 v) {
    float lo, hi;
    asm("mov.b64 {%0,%1}, %2;" : "=f"(lo), "=f"(hi) : "l"(v));
    return make_float2(lo, hi);
}
__device__ __forceinline__ void ffma2(u64 &acc, u64 a, u64 b) {
    asm("fma.rn.f32x2 %0, %1, %2, %0;" : "+l"(acc) : "l"(a), "l"(b));
}

// ---------- activations (fast intrinsics, rel err ~1e-6) ----------
__device__ __forceinline__ float softplus1(float x) {
    return fmaxf(x, 0.f) + __logf(1.f + __expf(-fabsf(x)));
}
__device__ __forceinline__ float sigmoid1(float x) {
    return __fdividef(1.f, 1.f + __expf(-x));
}
__device__ __forceinline__ float tanh1(float x) {
    return 1.f - __fdividef(2.f, __expf(2.f * x) + 1.f);
}

// Pack a row-major KxC=64 weight matrix into SMEM as float4 tiles:
// dst[(k/2)*32 + l] = { W[k][2l], W[k][2l+1], W[k+1][2l], W[k+1][2l+1] }
__device__ __forceinline__ void packW(float4* dst, const float* __restrict__ src,
                                      int K, int tid, int nthr) {
    int tot = (K >> 1) * 32;
    const float2* s = (const float2*)src;
    for (int i = tid; i < tot; i += nthr) {
        int m = i >> 5, l = i & 31;
        float2 a = s[(2 * m) * 32 + l];
        float2 b = s[(2 * m + 1) * 32 + l];
        dst[i] = make_float4(a.x, a.y, b.x, b.y);
    }
}

// =====================================================================
// Kernel 1: per-node precompute.
// P[n] = [ even[n]@W_em1[0:64]+b_em1 , even[n]@W_em1[64:128] ,
//          even[n]@W_ogh[0:64]+b_ogh , even[n]@W_ogh[64:128] ,
//          even[n]@W_pei+b_pei , even[n]@W_pej+b_pej ]
// =====================================================================
__global__ void __launch_bounds__(256, 1)
pre_kernel(const float* __restrict__ even,
           const float* __restrict__ W_em1, const float* __restrict__ W_ogh,
           const float* __restrict__ W_pei, const float* __restrict__ W_pej,
           const float* __restrict__ b_em1, const float* __restrict__ b_ogh,
           const float* __restrict__ b_pei, const float* __restrict__ b_pej)
{
    extern __shared__ float4 sm[];
    const int tid = threadIdx.x;
    packW(sm + 0,    W_em1,           64, tid, 256);
    packW(sm + 1024, W_em1 + 64 * 64, 64, tid, 256);
    packW(sm + 2048, W_ogh,           64, tid, 256);
    packW(sm + 3072, W_ogh + 64 * 64, 64, tid, 256);
    packW(sm + 4096, W_pei,           64, tid, 256);
    packW(sm + 5120, W_pej,           64, tid, 256);
    __syncthreads();

    const int lane = tid & 31;
    const int wid = tid >> 5;
    float4* xs = sm + 6144 + wid * 128;  // 4 nodes x 32 float4 staging

    float2 bias[6];
    bias[0] = ((const float2*)b_em1)[lane];
    bias[1] = make_float2(0.f, 0.f);
    bias[2] = ((const float2*)b_ogh)[lane];
    bias[3] = make_float2(0.f, 0.f);
    bias[4] = ((const float2*)b_pei)[lane];
    bias[5] = ((const float2*)b_pej)[lane];

    for (int g = blockIdx.x * 8 + wid; g < NN / 4; g += gridDim.x * 8) {
        int n0 = g * 4;
        __syncwarp();
        #pragma unroll
        for (int e = 0; e < 4; e++) {
            float2 v = ((const float2*)even)[(n0 + e) * 32 + lane];
            xs[e * 32 + lane] = make_float4(v.x, v.x, v.y, v.y);
        }
        __syncwarp();
        #pragma unroll
        for (int p = 0; p < 6; p++) {
            u64 acc[4];
            #pragma unroll
            for (int e = 0; e < 4; e++) acc[e] = pack2(bias[p].x, bias[p].y);
            #pragma unroll
            for (int m = 0; m < 32; m++) {
                ulonglong2 w = *(const ulonglong2*)(sm + p * 1024 + m * 32 + lane);
                #pragma unroll
                for (int e = 0; e < 4; e++) {
                    ulonglong2 x = *(const ulonglong2*)(xs + e * 32 + m);
                    ffma2(acc[e], x.x, w.x);
                    ffma2(acc[e], x.y, w.y);
                }
            }
            #pragma unroll
            for (int e = 0; e < 4; e++) {
                float2 r = unpack2(acc[e]);
                ((float2*)(g_P + (n0 + e) * 384 + p * 64))[lane] = r;
            }
        }
    }
}

// =====================================================================
// Kernel 2: per-edge fused MLP + aggregation. One warp per node,
// 5 batches of E=4 edges. All weights in SMEM (float4 2-row x 2-col
// interleave), per-edge activations staged as duplicated f32x2 pairs.
// =====================================================================
#define W_EM1T 0      // 48 m x 32 (rows 128..223 of W_em1)
#define W_OGHT 1536   // 48 m x 32
#define W_EG   3072   // 32 m x 32
#define W_EM2  4096
#define W_OG   5120
#define W_OM1  6144   // 64 m x 32
#define W_TOT  8192
#define AR_E   112    // float4 per edge arena
#define NWARP  12
#define MAIN_SMEM_F4 (W_TOT + NWARP * 4 * AR_E)   // 13568 f4 = 217088 B
#define PRE_SMEM_F4  (6144 + 8 * 128)             // 7168 f4 = 114688 B

__global__ void __launch_bounds__(NWARP * 32, 1)
edge_kernel(const float* __restrict__ even, const float* __restrict__ odd,
            const float* __restrict__ nbr, const int* __restrict__ idx,
            const float* __restrict__ W_em1, const float* __restrict__ W_ogh,
            const float* __restrict__ W_eg, const float* __restrict__ W_em2,
            const float* __restrict__ W_og, const float* __restrict__ W_om1,
            const float* __restrict__ b_eg, const float* __restrict__ b_em2,
            const float* __restrict__ b_og, float* __restrict__ out)
{
    extern __shared__ float4 sm[];
    const int tid = threadIdx.x;
    const int NT = NWARP * 32;
    packW(sm + W_EM1T, W_em1 + 128 * 64, 96, tid, NT);
    packW(sm + W_OGHT, W_ogh + 128 * 64, 96, tid, NT);
    packW(sm + W_EG,   W_eg,  64, tid, NT);
    packW(sm + W_EM2,  W_em2, 64, tid, NT);
    packW(sm + W_OG,   W_og,  64, tid, NT);
    packW(sm + W_OM1,  W_om1, 128, tid, NT);
    __syncthreads();

    const int lane = tid & 31;
    const int wid = tid >> 5;
    float4* arena = sm + W_TOT + wid * (4 * AR_E);
    // per edge e: [0..31] oc-dup (later omin[0:64] rows 0..63 via [0..63])
    //             [32..47] nbr-dup, [48..79] h-dup, [80..111] oh-dup

    const float2 beg  = ((const float2*)b_eg)[lane];
    const float2 bem2 = ((const float2*)b_em2)[lane];
    const float2 bog  = ((const float2*)b_og)[lane];

    #pragma unroll 1
    for (int n = blockIdx.x * NWARP + wid; n < NN; n += gridDim.x * NWARP) {
        const float2 oi   = ((const float2*)odd)[n * 32 + lane];
        const float2 em1i = ((const float2*)(g_P + n * 384      ))[lane];
        const float2 oghi = ((const float2*)(g_P + n * 384 + 128))[lane];
        const float2 pei  = ((const float2*)(g_P + n * 384 + 256))[lane];
        float2 aggE = make_float2(0.f, 0.f);
        float2 aggO = make_float2(0.f, 0.f);

        #pragma unroll 1
        for (int b = 0; b < 5; b++) {
            __syncwarp();
            int j[4];
            float2 oj[4];
            #pragma unroll
            for (int e = 0; e < 4; e++) j[e] = idx[n * MM + b * 4 + e];
            #pragma unroll
            for (int e = 0; e < 4; e++) {
                oj[e] = ((const float2*)odd)[j[e] * 32 + lane];
                float a0 = oi.x * oj[e].x, a1 = oi.y * oj[e].y;
                arena[e * AR_E + lane] = make_float4(a0, a0, a1, a1);
            }
            {   // nbr_fea staging: lanes 0..15 -> edges 0,1 ; lanes 16..31 -> edges 2,3
                int half = lane >> 4, ll = lane & 15;
                #pragma unroll
                for (int s = 0; s < 2; s++) {
                    int e = half * 2 + s;
                    float2 nv = ((const float2*)nbr)[(n * MM + b * 4 + e) * 16 + ll];
                    arena[e * AR_E + 32 + ll] = make_float4(nv.x, nv.x, nv.y, nv.y);
                }
            }
            __syncwarp();

            // ---- Stage A+C: h_pre (W_em1 tail) and oh_pre (W_ogh tail) ----
            u64 hacc[4], oacc[4];
            #pragma unroll
            for (int e = 0; e < 4; e++) {
                float2 e1j = ((const float2*)(g_P + j[e] * 384 +  64))[lane];
                float2 ogj = ((const float2*)(g_P + j[e] * 384 + 192))[lane];
                hacc[e] = pack2(em1i.x + e1j.x, em1i.y + e1j.y);
                oacc[e] = pack2(oghi.x + ogj.x, oghi.y + ogj.y);
            }
            #pragma unroll
            for (int m = 0; m < 16; m++) {  // nbr rows (32)
                ulonglong2 w1 = *(const ulonglong2*)(sm + W_EM1T + m * 32 + lane);
                ulonglong2 w2 = *(const ulonglong2*)(sm + W_OGHT + m * 32 + lane);
                #pragma unroll
                for (int e = 0; e < 4; e++) {
                    ulonglong2 x = *(const ulonglong2*)(arena + e * AR_E + 32 + m);
                    ffma2(hacc[e], x.x, w1.x); ffma2(hacc[e], x.y, w1.y);
                    ffma2(oacc[e], x.x, w2.x); ffma2(oacc[e], x.y, w2.y);
                }
            }
            #pragma unroll
            for (int m = 0; m < 32; m++) {  // odd_cross rows (64)
                ulonglong2 w1 = *(const ulonglong2*)(sm + W_EM1T + (16 + m) * 32 + lane);
                ulonglong2 w2 = *(const ulonglong2*)(sm + W_OGHT + (16 + m) * 32 + lane);
                #pragma unroll
                for (int e = 0; e < 4; e++) {
                    ulonglong2 x = *(const ulonglong2*)(arena + e * AR_E + m);
                    ffma2(hacc[e], x.x, w1.x); ffma2(hacc[e], x.y, w1.y);
                    ffma2(oacc[e], x.x, w2.x); ffma2(oacc[e], x.y, w2.y);
                }
            }
            #pragma unroll
            for (int e = 0; e < 4; e++) {
                float2 h = unpack2(hacc[e]);
                float h0 = softplus1(h.x), h1 = softplus1(h.y);
                arena[e * AR_E + 48 + lane] = make_float4(h0, h0, h1, h1);
                float2 q = unpack2(oacc[e]);
                float q0 = softplus1(q.x), q1 = softplus1(q.y);
                arena[e * AR_E + 80 + lane] = make_float4(q0, q0, q1, q1);
            }
            __syncwarp();

            // ---- Stage B: even gate & msg ----
            u64 gacc[4], macc[4];
            #pragma unroll
            for (int e = 0; e < 4; e++) {
                gacc[e] = pack2(beg.x, beg.y);
                macc[e] = pack2(bem2.x, bem2.y);
            }
            #pragma unroll
            for (int m = 0; m < 32; m++) {
                ulonglong2 wg = *(const ulonglong2*)(sm + W_EG  + m * 32 + lane);
                ulonglong2 wm = *(const ulonglong2*)(sm + W_EM2 + m * 32 + lane);
                #pragma unroll
                for (int e = 0; e < 4; e++) {
                    ulonglong2 x = *(const ulonglong2*)(arena + e * AR_E + 48 + m);
                    ffma2(gacc[e], x.x, wg.x); ffma2(gacc[e], x.y, wg.y);
                    ffma2(macc[e], x.x, wm.x); ffma2(macc[e], x.y, wm.y);
                }
            }
            #pragma unroll
            for (int e = 0; e < 4; e++) {
                float2 g = unpack2(gacc[e]);
                float2 q = unpack2(macc[e]);
                aggE.x += sigmoid1(g.x) * softplus1(q.x);
                aggE.y += sigmoid1(g.y) * softplus1(q.y);
            }

            // ---- Stage D: odd gate ----
            u64 oga[4];
            #pragma unroll
            for (int e = 0; e < 4; e++) oga[e] = pack2(bog.x, bog.y);
            #pragma unroll
            for (int m = 0; m < 32; m++) {
                ulonglong2 w = *(const ulonglong2*)(sm + W_OG + m * 32 + lane);
                #pragma unroll
                for (int e = 0; e < 4; e++) {
                    ulonglong2 x = *(const ulonglong2*)(arena + e * AR_E + 80 + m);
                    ffma2(oga[e], x.x, w.x); ffma2(oga[e], x.y, w.y);
                }
            }
            float2 ogate[4];
            #pragma unroll
            for (int e = 0; e < 4; e++) {
                float2 q = unpack2(oga[e]);
                ogate[e] = make_float2(sigmoid1(q.x), sigmoid1(q.y));
            }
            __syncwarp();

            // ---- Stage E: build [odd_ie | odd_ei] dup staging (reuses 0..63) ----
            #pragma unroll
            for (int e = 0; e < 4; e++) {
                float2 pj = ((const float2*)(g_P + j[e] * 384 + 320))[lane];
                float a0 = oi.x * pj.x, a1 = oi.y * pj.y;
                arena[e * AR_E + lane] = make_float4(a0, a0, a1, a1);
                float c0 = pei.x * oj[e].x, c1 = pei.y * oj[e].y;
                arena[e * AR_E + 32 + lane] = make_float4(c0, c0, c1, c1);
            }
            __syncwarp();

            // ---- Stage F: odd value = tanh([ie|ei] @ W_om1) ----
            u64 vacc[4];
            #pragma unroll
            for (int e = 0; e < 4; e++) vacc[e] = pack2(0.f, 0.f);
            #pragma unroll
            for (int m = 0; m < 64; m++) {
                ulonglong2 w = *(const ulonglong2*)(sm + W_OM1 + m * 32 + lane);
                #pragma unroll
                for (int e = 0; e < 4; e++) {
                    ulonglong2 x = *(const ulonglong2*)(arena + e * AR_E + m);
                    ffma2(vacc[e], x.x, w.x); ffma2(vacc[e], x.y, w.y);
                }
            }
            #pragma unroll
            for (int e = 0; e < 4; e++) {
                float2 v = unpack2(vacc[e]);
                aggO.x += ogate[e].x * tanh1(v.x);
                aggO.y += ogate[e].y * tanh1(v.y);
            }
        }

        float2 ev = ((const float2*)even)[n * 32 + lane];
        ((float2*)out)[n * 32 + lane] = make_float2(ev.x + aggE.x, ev.y + aggE.y);
        ((float2*)(out + NN * 64))[n * 32 + lane] = make_float2(oi.x + aggO.x, oi.y + aggO.y);
    }
}

extern "C" void kernel_launch(void* const* d_in, const int* in_sizes, int n_in,
                              void* d_out, int out_size) {
    const float* even  = (const float*)d_in[0];
    const float* odd   = (const float*)d_in[1];
    const float* nbr   = (const float*)d_in[2];
    const int*   idx   = (const int*)d_in[3];
    const float* W_em1 = (const float*)d_in[4];
    const float* b_em1 = (const float*)d_in[5];
    const float* W_eg  = (const float*)d_in[6];
    const float* b_eg  = (const float*)d_in[7];
    const float* W_em2 = (const float*)d_in[8];
    const float* b_em2 = (const float*)d_in[9];
    const float* W_pej = (const float*)d_in[10];
    const float* b_pej = (const float*)d_in[11];
    const float* W_pei = (const float*)d_in[12];
    const float* b_pei = (const float*)d_in[13];
    const float* W_om1 = (const float*)d_in[14];
    const float* W_ogh = (const float*)d_in[15];
    const float* b_ogh = (const float*)d_in[16];
    const float* W_og  = (const float*)d_in[17];
    const float* b_og  = (const float*)d_in[18];
    float* out = (float*)d_out;

    const int pre_smem  = PRE_SMEM_F4 * 16;
    const int main_smem = MAIN_SMEM_F4 * 16;
    cudaFuncSetAttribute(pre_kernel, cudaFuncAttributeMaxDynamicSharedMemorySize, pre_smem);
    cudaFuncSetAttribute(edge_kernel, cudaFuncAttributeMaxDynamicSharedMemorySize, main_smem);

    pre_kernel<<<148, 256, pre_smem>>>(even, W_em1, W_ogh, W_pei, W_pej,
                                       b_em1, b_ogh, b_pei, b_pej);
    edge_kernel<<<148, NWARP * 32, main_smem>>>(even, odd, nbr, idx,
                                                W_em1, W_ogh, W_eg, W_em2,
                                                W_og, W_om1, b_eg, b_em2, b_og, out);
}